// round 1
// baseline (speedup 1.0000x reference)
#include <cuda_runtime.h>
#include <cstdint>

// Problem constants
#define B_ROWS    1024
#define IN_FEAT   76800
#define IN_G      19200     // IN_FEAT/4 (float4 / int8x4 groups)
#define OUT_FEAT  10
#define W_ELEMS   (OUT_FEAT * IN_FEAT)   // 768000
#define W_G       (OUT_FEAT * IN_G)      // 192000 packed groups

// GEMV tiling
#define NSLICE    4
#define SLICE_G   (IN_G / NSLICE)        // 4800 groups per slice
#define ROWBLKS   148                    // one CTA row-block per SM-wave slot
#define GEMV_THREADS 960
#define GPT       (SLICE_G / GEMV_THREADS)   // 5 groups per thread

// wsum reduction
#define WSUM_BLOCKS 125
#define WSUM_THREADS 256

// ---------------- device scratch (static, allocation-free) ----------------
__device__ float    g_wpart[WSUM_BLOCKS];
__device__ float    g_wscale;               // 1/clip(mean|W|,eps)
__device__ float    g_winv;                 // clip(mean|W|,eps) = 1/wscale
__device__ float    g_rowscale[B_ROWS];     // 127/clip(rowmax,eps)
__device__ unsigned g_tw[W_G];              // ternary weights, packed int8x4, layout [o][g]
__device__ int      g_dot[B_ROWS * NSLICE * OUT_FEAT];

// ---------------- kernel 1: sum |W| ----------------
__global__ void k_wsum(const float4* __restrict__ w4) {
    float s = 0.f;
    int idx = blockIdx.x * WSUM_THREADS + threadIdx.x;
    #pragma unroll
    for (int k = 0; k < 6; k++) {   // 125*256*6 = 192000 exactly
        float4 v = w4[idx + k * WSUM_BLOCKS * WSUM_THREADS];
        s += fabsf(v.x) + fabsf(v.y) + fabsf(v.z) + fabsf(v.w);
    }
    // block reduce (deterministic tree)
    #pragma unroll
    for (int d = 16; d; d >>= 1) s += __shfl_down_sync(0xffffffffu, s, d);
    __shared__ float red[8];
    int warp = threadIdx.x >> 5, lane = threadIdx.x & 31;
    if (lane == 0) red[warp] = s;
    __syncthreads();
    if (threadIdx.x < 8) {
        float v = red[threadIdx.x];
        #pragma unroll
        for (int d = 4; d; d >>= 1) v += __shfl_down_sync(0xffu, v, d);
        if (threadIdx.x == 0) g_wpart[blockIdx.x] = v;
    }
}

// ---------------- kernel 2: finalize wscale ----------------
__global__ void k_wscale(void) {
    float s = (threadIdx.x < WSUM_BLOCKS) ? g_wpart[threadIdx.x] : 0.f;
    #pragma unroll
    for (int d = 16; d; d >>= 1) s += __shfl_down_sync(0xffffffffu, s, d);
    __shared__ float red[4];
    int warp = threadIdx.x >> 5, lane = threadIdx.x & 31;
    if (lane == 0) red[warp] = s;
    __syncthreads();
    if (threadIdx.x == 0) {
        float total = red[0] + red[1] + red[2] + red[3];
        float mean = fmaxf(total / (float)W_ELEMS, 1e-5f);
        g_winv = mean;
        g_wscale = 1.f / mean;
    }
}

// ---------------- kernel 3: ternarize W into packed int8x4 ----------------
__global__ void k_ternary(const float4* __restrict__ w4) {
    int i = blockIdx.x * 256 + threadIdx.x;   // grid 750*256 = 192000
    float ws = g_wscale;
    float4 v = w4[i];
    int t0 = (int)fminf(1.f, fmaxf(-1.f, rintf(v.x * ws)));
    int t1 = (int)fminf(1.f, fmaxf(-1.f, rintf(v.y * ws)));
    int t2 = (int)fminf(1.f, fmaxf(-1.f, rintf(v.z * ws)));
    int t3 = (int)fminf(1.f, fmaxf(-1.f, rintf(v.w * ws)));
    g_tw[i] = (unsigned)((t0 & 0xFF) | ((t1 & 0xFF) << 8) | ((t2 & 0xFF) << 16) | (t3 << 24));
}

// ---------------- kernel 4: per-row absmax -> activation scale ----------------
__global__ void __launch_bounds__(768) k_rowmax(const float4* __restrict__ x4) {
    int row = blockIdx.x;
    const float4* xr = x4 + (long)row * IN_G;
    float m = 0.f;
    #pragma unroll 5
    for (int k = 0; k < 25; k++) {   // 25*768 = 19200 exactly
        float4 v = xr[threadIdx.x + k * 768];
        m = fmaxf(m, fmaxf(fmaxf(fabsf(v.x), fabsf(v.y)), fmaxf(fabsf(v.z), fabsf(v.w))));
    }
    #pragma unroll
    for (int d = 16; d; d >>= 1) m = fmaxf(m, __shfl_down_sync(0xffffffffu, m, d));
    __shared__ float red[24];
    int warp = threadIdx.x >> 5, lane = threadIdx.x & 31;
    if (lane == 0) red[warp] = m;
    __syncthreads();
    if (threadIdx.x < 32) {
        float v = (threadIdx.x < 24) ? red[threadIdx.x] : 0.f;
        #pragma unroll
        for (int d = 16; d; d >>= 1) v = fmaxf(v, __shfl_down_sync(0xffffffffu, v, d));
        if (threadIdx.x == 0) g_rowscale[row] = 127.f / fmaxf(v, 1e-5f);
    }
}

// ---------------- kernel 5: fused quantize + ternary GEMV (int32-exact) ----------------
// grid (NSLICE, ROWBLKS); weights slice staged in dynamic smem, reused over rows.
__global__ void __launch_bounds__(GEMV_THREADS, 1) k_gemv(const float4* __restrict__ x4) {
    extern __shared__ unsigned smem[];
    unsigned* sw  = smem;                              // [10][SLICE_G]
    int*      sred = (int*)(smem + OUT_FEAT * SLICE_G); // [30][10]

    const int slice = blockIdx.x;
    const int tid = threadIdx.x;
    const int warp = tid >> 5, lane = tid & 31;

    // stage ternary weight slice into smem (coalesced, L2-resident source)
    const unsigned* twp = g_tw + slice * SLICE_G;
    #pragma unroll
    for (int o = 0; o < OUT_FEAT; o++) {
        #pragma unroll
        for (int k = 0; k < GPT; k++)
            sw[o * SLICE_G + tid + k * GEMV_THREADS] = twp[o * IN_G + tid + k * GEMV_THREADS];
    }
    __syncthreads();

    // row range for this CTA (592 CTAs = exactly 4 full waves on 148 SMs)
    int row_start = (blockIdx.y * B_ROWS) / ROWBLKS;
    int row_end   = ((blockIdx.y + 1) * B_ROWS) / ROWBLKS;

    for (int row = row_start; row < row_end; row++) {
        float as = g_rowscale[row];
        const float4* xr = x4 + (long)row * IN_G + slice * SLICE_G;

        // load + quantize this thread's 20 elements (|x*as| <= 127 always)
        unsigned q[GPT];
        #pragma unroll
        for (int k = 0; k < GPT; k++) {
            float4 v = xr[tid + k * GEMV_THREADS];
            int i0 = __float2int_rn(v.x * as);
            int i1 = __float2int_rn(v.y * as);
            int i2 = __float2int_rn(v.z * as);
            int i3 = __float2int_rn(v.w * as);
            q[k] = (unsigned)((i0 & 0xFF) | ((i1 & 0xFF) << 8) | ((i2 & 0xFF) << 16) | (i3 << 24));
        }

        int acc[OUT_FEAT];
        #pragma unroll
        for (int o = 0; o < OUT_FEAT; o++) acc[o] = 0;
        #pragma unroll
        for (int k = 0; k < GPT; k++) {
            int g = tid + k * GEMV_THREADS;
            #pragma unroll
            for (int o = 0; o < OUT_FEAT; o++)
                acc[o] = __dp4a((int)q[k], (int)sw[o * SLICE_G + g], acc[o]);
        }

        // reduce across 960 threads
        #pragma unroll
        for (int o = 0; o < OUT_FEAT; o++) {
            #pragma unroll
            for (int d = 16; d; d >>= 1)
                acc[o] += __shfl_down_sync(0xffffffffu, acc[o], d);
        }
        if (lane == 0) {
            #pragma unroll
            for (int o = 0; o < OUT_FEAT; o++) sred[warp * OUT_FEAT + o] = acc[o];
        }
        __syncthreads();
        if (tid < OUT_FEAT) {
            int s = 0;
            #pragma unroll
            for (int w = 0; w < GEMV_THREADS / 32; w++) s += sred[w * OUT_FEAT + tid];
            g_dot[(row * NSLICE + slice) * OUT_FEAT + tid] = s;
        }
        __syncthreads();   // protect sred reuse
    }
}

// ---------------- kernel 6: combine slices, scale, bias, softmax ----------------
__global__ void k_finish(const float* __restrict__ bias, float* __restrict__ out) {
    int row = blockIdx.x * 128 + threadIdx.x;   // grid 8 x 128 = 1024
    float inv_as = 1.f / g_rowscale[row];        // = clip(rowmax,eps)/127
    float coef = inv_as * g_winv;                // 1/(ascale*wscale)
    const int* dp = g_dot + row * NSLICE * OUT_FEAT;
    float logit[OUT_FEAT];
    float m = -3.4e38f;
    #pragma unroll
    for (int o = 0; o < OUT_FEAT; o++) {
        int d = dp[0 * OUT_FEAT + o] + dp[1 * OUT_FEAT + o]
              + dp[2 * OUT_FEAT + o] + dp[3 * OUT_FEAT + o];
        logit[o] = coef * (float)d + bias[o];
        m = fmaxf(m, logit[o]);
    }
    float s = 0.f;
    #pragma unroll
    for (int o = 0; o < OUT_FEAT; o++) { logit[o] = expf(logit[o] - m); s += logit[o]; }
    float inv_s = 1.f / s;
    #pragma unroll
    for (int o = 0; o < OUT_FEAT; o++) out[row * OUT_FEAT + o] = logit[o] * inv_s;
}

// ---------------- launch ----------------
extern "C" void kernel_launch(void* const* d_in, const int* in_sizes, int n_in,
                              void* d_out, int out_size) {
    const float4* x4 = (const float4*)d_in[0];   // [1024,3,160,160] fp32
    const float4* w4 = (const float4*)d_in[1];   // [10,76800] fp32
    const float*  b  = (const float*)d_in[2];    // [10]
    float* out = (float*)d_out;

    static int smem_set = 0;
    const int gemv_smem = OUT_FEAT * SLICE_G * 4 + (GEMV_THREADS / 32) * OUT_FEAT * 4; // 193200
    if (!smem_set) {
        cudaFuncSetAttribute(k_gemv, cudaFuncAttributeMaxDynamicSharedMemorySize, gemv_smem);
        smem_set = 1;
    }

    k_wsum<<<WSUM_BLOCKS, WSUM_THREADS>>>(w4);
    k_wscale<<<1, 128>>>();
    k_ternary<<<W_G / 256, 256>>>(w4);
    k_rowmax<<<B_ROWS, 768>>>(x4);
    dim3 ggrid(NSLICE, ROWBLKS);
    k_gemv<<<ggrid, GEMV_THREADS, gemv_smem>>>(x4);
    k_finish<<<B_ROWS / 128, 128>>>(b, out);
}